// round 12
// baseline (speedup 1.0000x reference)
#include <cuda_runtime.h>
#include <cuda_bf16.h>
#include <cstdint>

#define LL 16384
#define HH 1024
#define PP 512
#define NCHUNK 128
#define CHUNK 128

// ---- GEMM1: BM=128 BN=128 BK=64, fp32 A (direct u) + bf16 B, 4 stages ----
#define G1_AROW 272                    // 64 fp32 + 4 pad = 68 floats = 272B
#define G1_BROW 144                    // 64 bf16 + 8 pad = 144B
#define G1_AST (128 * G1_AROW)         // 34816
#define G1_BST (128 * G1_BROW)         // 18432
#define G1_STAGE (G1_AST + G1_BST)     // 53248
#define G1_SMEM (4 * G1_STAGE)         // 212992
#define G1_NK 16

// ---- GEMM2: BM=128 BN=128 BK=128 bf16/bf16, 3 stages (R11 proven) ----
#define G2_ROWB 272                    // 128 bf16 + 8 pad = 272B
#define G2_ABYTES (128 * G2_ROWB)      // 34816
#define G2_STAGE (2 * G2_ABYTES)       // 69632
#define G2_SMEM (3 * G2_STAGE)         // 208896
#define G2_NK 8

// ---------------- scratch (device globals) ----------------
__device__ float2 g_Lam[PP];
__device__ float2 g_F[PP];
__device__ __nv_bfloat16 g_Bcat[(size_t)(2 * PP) * HH];   // rows 0..511 Bbar_re, 512..1023 Bbar_im
__device__ __nv_bfloat16 g_Ccat[(size_t)HH * (2 * PP)];   // row h: [0..511]=C_re, [512..1023]=C_im
__device__ __nv_bfloat16 g_Bu[(size_t)LL * (2 * PP)];
__device__ __nv_bfloat16 g_X[(size_t)LL * (2 * PP)];      // row l: [0..511]=x_re, [512..1023]=x_im
__device__ float2 g_End[NCHUNK * PP];
__device__ float2 g_Carry[NCHUNK * PP];

// ---------------- helpers ----------------
__device__ __forceinline__ uint32_t smem_u32(const void* p) {
    uint32_t a;
    asm("{ .reg .u64 t; cvta.to.shared.u64 t, %1; cvt.u32.u64 %0, t; }" : "=r"(a) : "l"(p));
    return a;
}
__device__ __forceinline__ void cp_async16(uint32_t smem_dst, const void* gmem_src) {
    asm volatile("cp.async.cg.shared.global [%0], [%1], 16;\n" :: "r"(smem_dst), "l"(gmem_src));
}
__device__ __forceinline__ void cp_commit() { asm volatile("cp.async.commit_group;\n"); }

__device__ __forceinline__ void ldsm_x4(unsigned* r, uint32_t addr) {
    asm volatile("ldmatrix.sync.aligned.m8n8.x4.shared.b16 {%0,%1,%2,%3}, [%4];"
                 : "=r"(r[0]), "=r"(r[1]), "=r"(r[2]), "=r"(r[3]) : "r"(addr));
}
__device__ __forceinline__ void mma16816(float* d, const unsigned* a, const unsigned* b) {
    asm volatile(
        "mma.sync.aligned.m16n8k16.row.col.f32.bf16.bf16.f32 "
        "{%0,%1,%2,%3}, {%4,%5,%6,%7}, {%8,%9}, {%0,%1,%2,%3};\n"
        : "+f"(d[0]), "+f"(d[1]), "+f"(d[2]), "+f"(d[3])
        : "r"(a[0]), "r"(a[1]), "r"(a[2]), "r"(a[3]), "r"(b[0]), "r"(b[1]));
}
// pack two fp32 -> bf16x2 with RN rounding (lo = first k-element, hi = second)
__device__ __forceinline__ unsigned pack_bf16x2(float lo, float hi) {
    unsigned r;
    asm("cvt.rn.bf16x2.f32 %0, %1, %2;" : "=r"(r) : "f"(hi), "f"(lo));
    return r;
}

// ---------------- prep kernels ----------------
__global__ void prep_lambda_kernel(const float* __restrict__ Lre,
                                   const float* __restrict__ Lim,
                                   const float* __restrict__ logstep) {
    int p = threadIdx.x;
    if (p >= PP) return;
    double step = exp((double)logstep[p]);
    double lr = (double)Lre[p], li = (double)Lim[p];
    double a = lr * step, b = li * step;
    double er = exp(a);
    double s = sin(b), c = cos(b);
    float Lbr = (float)(er * c), Lbi = (float)(er * s);
    g_Lam[p] = make_float2(Lbr, Lbi);
    double dr = (double)Lbr - 1.0, di = (double)Lbi;
    double den = lr * lr + li * li;
    float fr = (float)((dr * lr + di * li) / den);
    float fi = (float)((di * lr - dr * li) / den);
    g_F[p] = make_float2(fr, fi);
}

// merged B + C prep (one launch)
__global__ void prep_BC_kernel(const float* __restrict__ B_re, const float* __restrict__ B_im,
                               const float* __restrict__ C_re, const float* __restrict__ C_im) {
    int i = blockIdx.x * blockDim.x + threadIdx.x;
    if (i >= PP * HH) return;
    {
        int p = i >> 10, h = i & 1023;
        float2 f = g_F[p];
        float br = B_re[i], bi = B_im[i];
        float re = f.x * br - f.y * bi;
        float im = f.x * bi + f.y * br;
        g_Bcat[(size_t)p * HH + h]        = __float2bfloat16_rn(re);
        g_Bcat[(size_t)(PP + p) * HH + h] = __float2bfloat16_rn(im);
    }
    {
        int h = i >> 9, p = i & 511;
        g_Ccat[(size_t)h * 1024 + p]       = __float2bfloat16_rn(C_re[i]);
        g_Ccat[(size_t)h * 1024 + 512 + p] = __float2bfloat16_rn(C_im[i]);
    }
}

// ---------------- GEMM1: Bu = bf16(u) @ Bcat^T (K=1024), fp32 A loaded directly ----------------
// 512 thr (16 warps 4x4), warp tile 32x32, BK=64, 4 stages
__global__ __launch_bounds__(512, 1)
void gemm1_kernel(const float* __restrict__ u) {
    extern __shared__ __align__(16) char smem[];
    const uint32_t smem_base = smem_u32(smem);
    const int tid = threadIdx.x;
    const int warp = tid >> 5, lane = tid & 31;
    const int wm = warp >> 2, wn = warp & 3;
    const int g = lane >> 2, t = lane & 3;
    const int bm = blockIdx.x * 128;
    const int bn = blockIdx.y * 128;

    float acc[2][4][4];
    #pragma unroll
    for (int i = 0; i < 2; i++)
        #pragma unroll
        for (int j = 0; j < 4; j++)
            #pragma unroll
            for (int k = 0; k < 4; k++) acc[i][j][k] = 0.f;

    // A fp32 per-lane base (bytes): row (wm*32+g), col 2t
    const uint32_t aA_off = (uint32_t)((wm * 32 + g) * G1_AROW + t * 8);
    // B ldmatrix per-lane base, stride 144B
    const int tI = lane >> 3, tr = lane & 7;
    const uint32_t b_off = (uint32_t)((wn * 32 + (tI >> 1) * 8 + tr) * G1_BROW + (tI & 1) * 16);

    // stage loader: A 2048 chunks (fp32) + B 1024 chunks (bf16), 6 per thread
    auto load_stage = [&](int s) {
        const uint32_t base = smem_base + (uint32_t)(s & 3) * G1_STAGE;
        const int kc = s * 64;
        #pragma unroll
        for (int j = 0; j < 6; j++) {
            int idx = tid + j * 512;
            if (idx < 2048) {
                int row = idx >> 4, ch = idx & 15;
                uint32_t dst = base + (uint32_t)row * G1_AROW + (uint32_t)ch * 16;
                cp_async16(dst, u + (size_t)(bm + row) * 1024 + kc + ch * 4);
            } else {
                int loc = idx - 2048;
                int row = loc >> 3, ch = loc & 7;
                uint32_t dst = base + G1_AST + (uint32_t)row * G1_BROW + (uint32_t)ch * 16;
                cp_async16(dst, g_Bcat + (size_t)(bn + row) * 1024 + kc + ch * 8);
            }
        }
        cp_commit();
    };

    load_stage(0); load_stage(1); load_stage(2);

    for (int ks = 0; ks < G1_NK; ks++) {
        {
            int rem = G1_NK - 1 - ks;
            if (rem >= 2)      asm volatile("cp.async.wait_group 2;\n");
            else if (rem == 1) asm volatile("cp.async.wait_group 1;\n");
            else               asm volatile("cp.async.wait_group 0;\n");
        }
        __syncthreads();
        if (ks + 3 < G1_NK) load_stage(ks + 3);

        const uint32_t As = smem_base + (uint32_t)(ks & 3) * G1_STAGE;
        const uint32_t Bs = As + G1_AST;
        const char* Asp = smem + ((ks & 3) * G1_STAGE);
        #pragma unroll
        for (int kk = 0; kk < 64; kk += 16) {
            unsigned af[2][4], bf[4][2];
            #pragma unroll
            for (int mt = 0; mt < 2; mt++) {
                const char* pa = Asp + aA_off + mt * 16 * G1_AROW + kk * 4;
                float2 v0 = *(const float2*)(pa);                       // (row, k0)
                float2 v1 = *(const float2*)(pa + 8 * G1_AROW);         // (row+8, k0)
                float2 v2 = *(const float2*)(pa + 32);                  // (row, k0+8)
                float2 v3 = *(const float2*)(pa + 8 * G1_AROW + 32);    // (row+8, k0+8)
                af[mt][0] = pack_bf16x2(v0.x, v0.y);
                af[mt][1] = pack_bf16x2(v1.x, v1.y);
                af[mt][2] = pack_bf16x2(v2.x, v2.y);
                af[mt][3] = pack_bf16x2(v3.x, v3.y);
            }
            #pragma unroll
            for (int q = 0; q < 2; q++) {
                unsigned r[4];
                ldsm_x4(r, Bs + b_off + (uint32_t)(q * 16 * G1_BROW) + (uint32_t)(kk * 2));
                bf[2 * q][0] = r[0]; bf[2 * q][1] = r[1];
                bf[2 * q + 1][0] = r[2]; bf[2 * q + 1][1] = r[3];
            }
            #pragma unroll
            for (int mt = 0; mt < 2; mt++)
                #pragma unroll
                for (int nt = 0; nt < 4; nt++)
                    mma16816(acc[mt][nt], af[mt], bf[nt]);
        }
    }

    #pragma unroll
    for (int mt = 0; mt < 2; mt++) {
        #pragma unroll
        for (int nt = 0; nt < 4; nt++) {
            int r0 = bm + wm * 32 + mt * 16 + g;
            int c0 = bn + wn * 32 + nt * 8 + 2 * t;
            __nv_bfloat162 v;
            v.x = __float2bfloat16_rn(acc[mt][nt][0]);
            v.y = __float2bfloat16_rn(acc[mt][nt][1]);
            *(__nv_bfloat162*)&g_Bu[(size_t)r0 * 1024 + c0] = v;
            v.x = __float2bfloat16_rn(acc[mt][nt][2]);
            v.y = __float2bfloat16_rn(acc[mt][nt][3]);
            *(__nv_bfloat162*)&g_Bu[(size_t)(r0 + 8) * 1024 + c0] = v;
        }
    }
}

// ---------------- GEMM2 (R11 proven): BM=128 BN=128 BK=128, 3 stages ----------------
// ks 0..3: rr = x_re @ C_re^T -> round bf16, stash; ks 4..7: ii = x_im @ C_im^T
// out = 2*float(bf16(rr) - bf16(ii)) + D*u
__global__ __launch_bounds__(512, 1)
void gemm2_kernel(const float* __restrict__ u, const float* __restrict__ Dv,
                  float* __restrict__ out) {
    extern __shared__ __align__(16) char smem[];
    const uint32_t smem_base = smem_u32(smem);
    const int tid = threadIdx.x;
    const int warp = tid >> 5, lane = tid & 31;
    const int wm = warp >> 2, wn = warp & 3;
    const int g = lane >> 2, t = lane & 3;
    const int bm = blockIdx.x * 128;
    const int bn = blockIdx.y * 128;

    float acc[2][4][4];
    #pragma unroll
    for (int i = 0; i < 2; i++)
        #pragma unroll
        for (int j = 0; j < 4; j++)
            #pragma unroll
            for (int k = 0; k < 4; k++) acc[i][j][k] = 0.f;
    uint32_t rrs[2][4][2];

    const int tI = lane >> 3, tr = lane & 7;
    const uint32_t a_off = (uint32_t)((wm * 32 + (tI & 1) * 8 + tr) * G2_ROWB + (tI >> 1) * 16);
    const uint32_t b_off = (uint32_t)((wn * 32 + (tI >> 1) * 8 + tr) * G2_ROWB + (tI & 1) * 16);

    auto load_stage = [&](int s) {
        const uint32_t base = smem_base + (uint32_t)(s % 3) * G2_STAGE;
        const int kc = s * 128;
        #pragma unroll
        for (int j = 0; j < 8; j++) {
            int idx = tid + j * 512;
            int mat = idx >> 11;
            int loc = idx & 2047;
            int row = loc >> 4, ch = loc & 15;
            uint32_t dst = base + (uint32_t)mat * G2_ABYTES + (uint32_t)row * G2_ROWB + (uint32_t)ch * 16;
            const __nv_bfloat16* src = (mat ? g_Ccat + (size_t)(bn + row) * 1024
                                            : g_X + (size_t)(bm + row) * 1024) + kc + ch * 8;
            cp_async16(dst, src);
        }
        cp_commit();
    };

    load_stage(0); load_stage(1);

    for (int ks = 0; ks < G2_NK; ks++) {
        if (ks < G2_NK - 1) asm volatile("cp.async.wait_group 1;\n");
        else                asm volatile("cp.async.wait_group 0;\n");
        __syncthreads();
        if (ks + 2 < G2_NK) load_stage(ks + 2);

        const uint32_t As = smem_base + (uint32_t)(ks % 3) * G2_STAGE;
        const uint32_t Bs = As + G2_ABYTES;
        #pragma unroll
        for (int kk = 0; kk < 128; kk += 16) {
            unsigned af[2][4], bf[4][2];
            #pragma unroll
            for (int mt = 0; mt < 2; mt++)
                ldsm_x4(af[mt], As + a_off + (uint32_t)(mt * 16 * G2_ROWB) + (uint32_t)(kk * 2));
            #pragma unroll
            for (int q = 0; q < 2; q++) {
                unsigned r[4];
                ldsm_x4(r, Bs + b_off + (uint32_t)(q * 16 * G2_ROWB) + (uint32_t)(kk * 2));
                bf[2 * q][0] = r[0]; bf[2 * q][1] = r[1];
                bf[2 * q + 1][0] = r[2]; bf[2 * q + 1][1] = r[3];
            }
            #pragma unroll
            for (int mt = 0; mt < 2; mt++)
                #pragma unroll
                for (int nt = 0; nt < 4; nt++)
                    mma16816(acc[mt][nt], af[mt], bf[nt]);
        }

        if (ks == 3) {
            #pragma unroll
            for (int mt = 0; mt < 2; mt++)
                #pragma unroll
                for (int nt = 0; nt < 4; nt++) {
                    __nv_bfloat162 v0, v1;
                    v0.x = __float2bfloat16_rn(acc[mt][nt][0]);
                    v0.y = __float2bfloat16_rn(acc[mt][nt][1]);
                    v1.x = __float2bfloat16_rn(acc[mt][nt][2]);
                    v1.y = __float2bfloat16_rn(acc[mt][nt][3]);
                    rrs[mt][nt][0] = *(uint32_t*)&v0;
                    rrs[mt][nt][1] = *(uint32_t*)&v1;
                    acc[mt][nt][0] = 0.f; acc[mt][nt][1] = 0.f;
                    acc[mt][nt][2] = 0.f; acc[mt][nt][3] = 0.f;
                }
        }
    }

    #pragma unroll
    for (int mt = 0; mt < 2; mt++) {
        #pragma unroll
        for (int nt = 0; nt < 4; nt++) {
            int r0 = bm + wm * 32 + mt * 16 + g;
            int c0 = bn + wn * 32 + nt * 8 + 2 * t;
            float d0 = __ldg(Dv + c0), d1 = __ldg(Dv + c0 + 1);
            #pragma unroll
            for (int half = 0; half < 2; half++) {
                int row = r0 + half * 8;
                __nv_bfloat162 rrv = *(__nv_bfloat162*)&rrs[mt][nt][half];
                __nv_bfloat16 ii0 = __float2bfloat16_rn(acc[mt][nt][2 * half]);
                __nv_bfloat16 ii1 = __float2bfloat16_rn(acc[mt][nt][2 * half + 1]);
                float db0 = __bfloat162float(__hsub(rrv.x, ii0));
                float db1 = __bfloat162float(__hsub(rrv.y, ii1));
                const float2 uu = *(const float2*)(u + (size_t)row * 1024 + c0);
                float2 ov;
                ov.x = fmaf(2.f, db0, d0 * uu.x);
                ov.y = fmaf(2.f, db1, d1 * uu.y);
                *(float2*)(out + (size_t)row * 1024 + c0) = ov;
            }
        }
    }
}

// ---------------- scan (R9/R11 proven) ----------------
__global__ void scan_pass1() {
    int p = threadIdx.x;
    int c = blockIdx.x;
    float2 Lam = g_Lam[p];
    float xr = 0.f, xi = 0.f;
    const __nv_bfloat16* bu = g_Bu + (size_t)c * CHUNK * 1024;
    for (int tt = 0; tt < CHUNK; tt++) {
        float br = __bfloat162float(bu[tt * 1024 + p]);
        float bi = __bfloat162float(bu[tt * 1024 + 512 + p]);
        float nr = fmaf(Lam.x, xr, fmaf(-Lam.y, xi, br));
        float ni = fmaf(Lam.x, xi, fmaf(Lam.y, xr, bi));
        xr = nr; xi = ni;
    }
    g_End[c * PP + p] = make_float2(xr, xi);
}

__global__ __launch_bounds__(512) void scan_pass2_par() {
    __shared__ float2 buf[512];
    const int t = threadIdx.x;
    const int ch = t >> 7;
    const int c  = t & 127;
    const int p  = blockIdx.x * 4 + ch;
    float2 Lam = g_Lam[p];
    float wr = Lam.x, wi = Lam.y;
    #pragma unroll
    for (int s = 0; s < 7; s++) {
        float nr = wr * wr - wi * wi;
        float ni = 2.f * wr * wi;
        wr = nr; wi = ni;
    }
    float2 v = g_End[c * PP + p];
    float cr = wr, ci = wi;
    #pragma unroll
    for (int d = 1; d < 128; d <<= 1) {
        buf[t] = v;
        __syncthreads();
        if (c >= d) {
            float2 u2 = buf[t - d];
            float nx = fmaf(cr, u2.x, fmaf(-ci, u2.y, v.x));
            float ny = fmaf(cr, u2.y, fmaf(ci, u2.x, v.y));
            v.x = nx; v.y = ny;
        }
        __syncthreads();
        float nr = cr * cr - ci * ci;
        float ni = 2.f * cr * ci;
        cr = nr; ci = ni;
    }
    buf[t] = v;
    __syncthreads();
    float2 carry = (c == 0) ? make_float2(0.f, 0.f) : buf[t - 1];
    g_Carry[c * PP + p] = carry;
}

__global__ void scan_pass3() {
    int p = threadIdx.x;
    int c = blockIdx.x;
    float2 Lam = g_Lam[p];
    float2 cin = g_Carry[c * PP + p];
    float xr = cin.x, xi = cin.y;
    const __nv_bfloat16* bu = g_Bu + (size_t)c * CHUNK * 1024;
    __nv_bfloat16* xo = g_X + (size_t)c * CHUNK * 1024;
    for (int tt = 0; tt < CHUNK; tt++) {
        float br = __bfloat162float(bu[tt * 1024 + p]);
        float bi = __bfloat162float(bu[tt * 1024 + 512 + p]);
        float nr = fmaf(Lam.x, xr, fmaf(-Lam.y, xi, br));
        float ni = fmaf(Lam.x, xi, fmaf(Lam.y, xr, bi));
        xr = nr; xi = ni;
        xo[tt * 1024 + p]       = __float2bfloat16_rn(xr);
        xo[tt * 1024 + 512 + p] = __float2bfloat16_rn(xi);
    }
}

// ---------------- launch ----------------
extern "C" void kernel_launch(void* const* d_in, const int* in_sizes, int n_in,
                              void* d_out, int out_size) {
    const float* u       = (const float*)d_in[0];
    const float* LamRe   = (const float*)d_in[1];
    const float* LamIm   = (const float*)d_in[2];
    const float* B_re    = (const float*)d_in[3];
    const float* B_im    = (const float*)d_in[4];
    const float* C_re    = (const float*)d_in[5];
    const float* C_im    = (const float*)d_in[6];
    const float* Dv      = (const float*)d_in[7];
    const float* logstep = (const float*)d_in[8];
    float* out = (float*)d_out;

    prep_lambda_kernel<<<1, 512>>>(LamRe, LamIm, logstep);
    prep_BC_kernel<<<(PP * HH) / 256, 256>>>(B_re, B_im, C_re, C_im);

    cudaFuncSetAttribute(gemm1_kernel, cudaFuncAttributeMaxDynamicSharedMemorySize, G1_SMEM);
    gemm1_kernel<<<dim3(LL / 128, 8), 512, G1_SMEM>>>(u);

    scan_pass1<<<NCHUNK, PP>>>();
    scan_pass2_par<<<NCHUNK, 512>>>();
    scan_pass3<<<NCHUNK, PP>>>();

    cudaFuncSetAttribute(gemm2_kernel, cudaFuncAttributeMaxDynamicSharedMemorySize, G2_SMEM);
    gemm2_kernel<<<dim3(LL / 128, 8), 512, G2_SMEM>>>(u, Dv, out);
}

// round 13
// speedup vs baseline: 1.3330x; 1.3330x over previous
#include <cuda_runtime.h>
#include <cuda_bf16.h>
#include <cstdint>

#define LL 16384
#define HH 1024
#define PP 512
#define NCHUNK 256
#define CHUNK 64

// ---- HMMA GEMM config: BM=128 BN=128 BK=128, 3 stages (R11 proven) ----
#define ROWB 272                      // 128 bf16 + 8 pad = 272B (272%128=16: conflict-free)
#define A_BYTES (128 * ROWB)          // 34816
#define STAGE_B (2 * A_BYTES)         // 69632
#define GSMEM (3 * STAGE_B)           // 208896 (< 227KB)
#define GNK 8                         // K iters of 128 (both GEMMs span 1024 cols)

// ---------------- scratch (device globals) ----------------
__device__ float2 g_Lam[PP];
__device__ float2 g_F[PP];
__device__ __nv_bfloat16 g_U[(size_t)LL * HH];
__device__ __nv_bfloat16 g_Bcat[(size_t)(2 * PP) * HH];   // rows 0..511 Bbar_re, 512..1023 Bbar_im
__device__ __nv_bfloat16 g_Ccat[(size_t)HH * (2 * PP)];   // row h: [0..511]=C_re, [512..1023]=C_im
__device__ __nv_bfloat16 g_Bu[(size_t)LL * (2 * PP)];
__device__ __nv_bfloat16 g_X[(size_t)LL * (2 * PP)];      // row l: [0..511]=x_re, [512..1023]=x_im
__device__ float2 g_End[NCHUNK * PP];
__device__ float2 g_Carry[NCHUNK * PP];

// ---------------- helpers ----------------
__device__ __forceinline__ uint32_t smem_u32(const void* p) {
    uint32_t a;
    asm("{ .reg .u64 t; cvta.to.shared.u64 t, %1; cvt.u32.u64 %0, t; }" : "=r"(a) : "l"(p));
    return a;
}
__device__ __forceinline__ void cp_async16(uint32_t smem_dst, const void* gmem_src) {
    asm volatile("cp.async.cg.shared.global [%0], [%1], 16;\n" :: "r"(smem_dst), "l"(gmem_src));
}
__device__ __forceinline__ void cp_commit() { asm volatile("cp.async.commit_group;\n"); }

__device__ __forceinline__ void ldsm_x4(unsigned* r, uint32_t addr) {
    asm volatile("ldmatrix.sync.aligned.m8n8.x4.shared.b16 {%0,%1,%2,%3}, [%4];"
                 : "=r"(r[0]), "=r"(r[1]), "=r"(r[2]), "=r"(r[3]) : "r"(addr));
}
__device__ __forceinline__ void mma16816(float* d, const unsigned* a, const unsigned* b) {
    asm volatile(
        "mma.sync.aligned.m16n8k16.row.col.f32.bf16.bf16.f32 "
        "{%0,%1,%2,%3}, {%4,%5,%6,%7}, {%8,%9}, {%0,%1,%2,%3};\n"
        : "+f"(d[0]), "+f"(d[1]), "+f"(d[2]), "+f"(d[3])
        : "r"(a[0]), "r"(a[1]), "r"(a[2]), "r"(a[3]), "r"(b[0]), "r"(b[1]));
}

// ---------------- prep kernels ----------------
__global__ void prep_lambda_kernel(const float* __restrict__ Lre,
                                   const float* __restrict__ Lim,
                                   const float* __restrict__ logstep) {
    int p = threadIdx.x;
    if (p >= PP) return;
    double step = exp((double)logstep[p]);
    double lr = (double)Lre[p], li = (double)Lim[p];
    double a = lr * step, b = li * step;
    double er = exp(a);
    double s = sin(b), c = cos(b);
    float Lbr = (float)(er * c), Lbi = (float)(er * s);
    g_Lam[p] = make_float2(Lbr, Lbi);
    double dr = (double)Lbr - 1.0, di = (double)Lbi;
    double den = lr * lr + li * li;
    float fr = (float)((dr * lr + di * li) / den);
    float fi = (float)((di * lr - dr * li) / den);
    g_F[p] = make_float2(fr, fi);
}

// merged B + C prep (one launch)
__global__ void prep_BC_kernel(const float* __restrict__ B_re, const float* __restrict__ B_im,
                               const float* __restrict__ C_re, const float* __restrict__ C_im) {
    int i = blockIdx.x * blockDim.x + threadIdx.x;
    if (i >= PP * HH) return;
    {
        int p = i >> 10, h = i & 1023;
        float2 f = g_F[p];
        float br = B_re[i], bi = B_im[i];
        float re = f.x * br - f.y * bi;
        float im = f.x * bi + f.y * br;
        g_Bcat[(size_t)p * HH + h]        = __float2bfloat16_rn(re);
        g_Bcat[(size_t)(PP + p) * HH + h] = __float2bfloat16_rn(im);
    }
    {
        int h = i >> 9, p = i & 511;
        g_Ccat[(size_t)h * 1024 + p]       = __float2bfloat16_rn(C_re[i]);
        g_Ccat[(size_t)h * 1024 + 512 + p] = __float2bfloat16_rn(C_im[i]);
    }
}

// 8 floats per thread -> one 16B bf16 store
__global__ void prep_U_kernel(const float* __restrict__ u) {
    int i = blockIdx.x * blockDim.x + threadIdx.x;
    if (i >= (LL * HH) / 8) return;
    float4 v0 = ((const float4*)u)[2 * (size_t)i];
    float4 v1 = ((const float4*)u)[2 * (size_t)i + 1];
    __nv_bfloat162 a, b, c, d;
    a.x = __float2bfloat16_rn(v0.x); a.y = __float2bfloat16_rn(v0.y);
    b.x = __float2bfloat16_rn(v0.z); b.y = __float2bfloat16_rn(v0.w);
    c.x = __float2bfloat16_rn(v1.x); c.y = __float2bfloat16_rn(v1.y);
    d.x = __float2bfloat16_rn(v1.z); d.y = __float2bfloat16_rn(v1.w);
    uint4 pk = make_uint4(*(uint32_t*)&a, *(uint32_t*)&b, *(uint32_t*)&c, *(uint32_t*)&d);
    ((uint4*)g_U)[i] = pk;
}

// ---------------- HMMA GEMM: BM=128 BN=128 BK=128, 512 thr (16 warps 4x4), warp tile 32x32 ----------------
// MODE 0: Bu = u_bf @ Bcat^T  (K=1024), bf16 out
// MODE 1: phase0 (ks 0..3):  rr = x_re @ C_re^T  -> round to bf16, stash
//         phase1 (ks 4..7):  ii = x_im @ C_im^T
//         out = 2*float(bf16(rr) - bf16(ii)) + D*u, fp32 out
template <int MODE>
__global__ __launch_bounds__(512, 1)
void gemm_hmma_kernel(const float* __restrict__ u, const float* __restrict__ Dv,
                      float* __restrict__ out) {
    extern __shared__ __align__(16) char smem[];
    const uint32_t smem_base = smem_u32(smem);
    const int tid = threadIdx.x;
    const int warp = tid >> 5, lane = tid & 31;
    const int wm = warp >> 2, wn = warp & 3;     // 4 x 4 warps, warp tile 32x32
    const int g = lane >> 2, t = lane & 3;
    const int bm = blockIdx.x * 128;
    const int bn = blockIdx.y * 128;
    const __nv_bfloat16* Asrc = (MODE == 0) ? g_U : g_X;
    const __nv_bfloat16* Bsrc = (MODE == 0) ? g_Bcat : g_Ccat;

    float acc[2][4][4];
    #pragma unroll
    for (int i = 0; i < 2; i++)
        #pragma unroll
        for (int j = 0; j < 4; j++)
            #pragma unroll
            for (int k = 0; k < 4; k++) acc[i][j][k] = 0.f;
    uint32_t rrs[2][4][2];   // MODE1: stashed bf16(rr)

    const int tI = lane >> 3, tr = lane & 7;
    const uint32_t a_off = (uint32_t)((wm * 32 + (tI & 1) * 8 + tr) * ROWB + (tI >> 1) * 16);
    const uint32_t b_off = (uint32_t)((wn * 32 + (tI >> 1) * 8 + tr) * ROWB + (tI & 1) * 16);

    // ---- stage loader: A 2048 chunks + B 2048 chunks of 16B, 8 per thread ----
    auto load_stage = [&](int s) {
        const uint32_t base = smem_base + (uint32_t)(s % 3) * STAGE_B;
        const int kc = s * 128;
        #pragma unroll
        for (int j = 0; j < 8; j++) {
            int idx = tid + j * 512;
            int mat = idx >> 11;            // 0 = A, 1 = B (constant per j)
            int loc = idx & 2047;
            int row = loc >> 4, ch = loc & 15;
            uint32_t dst = base + (uint32_t)mat * A_BYTES + (uint32_t)row * ROWB + (uint32_t)ch * 16;
            const __nv_bfloat16* src = (mat ? Bsrc + (size_t)(bn + row) * 1024
                                            : Asrc + (size_t)(bm + row) * 1024) + kc + ch * 8;
            cp_async16(dst, src);
        }
        cp_commit();
    };

    load_stage(0); load_stage(1);

    for (int ks = 0; ks < GNK; ks++) {
        if (ks < GNK - 1) asm volatile("cp.async.wait_group 1;\n");
        else              asm volatile("cp.async.wait_group 0;\n");
        __syncthreads();
        if (ks + 2 < GNK) load_stage(ks + 2);

        const uint32_t As = smem_base + (uint32_t)(ks % 3) * STAGE_B;
        const uint32_t Bs = As + A_BYTES;
        #pragma unroll
        for (int kk = 0; kk < 128; kk += 16) {
            unsigned af[2][4], bf[4][2];
            #pragma unroll
            for (int mt = 0; mt < 2; mt++)
                ldsm_x4(af[mt], As + a_off + (uint32_t)(mt * 16 * ROWB) + (uint32_t)(kk * 2));
            #pragma unroll
            for (int q = 0; q < 2; q++) {
                unsigned r[4];
                ldsm_x4(r, Bs + b_off + (uint32_t)(q * 16 * ROWB) + (uint32_t)(kk * 2));
                bf[2 * q][0] = r[0]; bf[2 * q][1] = r[1];
                bf[2 * q + 1][0] = r[2]; bf[2 * q + 1][1] = r[3];
            }
            #pragma unroll
            for (int mt = 0; mt < 2; mt++)
                #pragma unroll
                for (int nt = 0; nt < 4; nt++)
                    mma16816(acc[mt][nt], af[mt], bf[nt]);
        }

        if (MODE == 1 && ks == 3) {
            #pragma unroll
            for (int mt = 0; mt < 2; mt++)
                #pragma unroll
                for (int nt = 0; nt < 4; nt++) {
                    __nv_bfloat162 v0, v1;
                    v0.x = __float2bfloat16_rn(acc[mt][nt][0]);
                    v0.y = __float2bfloat16_rn(acc[mt][nt][1]);
                    v1.x = __float2bfloat16_rn(acc[mt][nt][2]);
                    v1.y = __float2bfloat16_rn(acc[mt][nt][3]);
                    rrs[mt][nt][0] = *(uint32_t*)&v0;
                    rrs[mt][nt][1] = *(uint32_t*)&v1;
                    acc[mt][nt][0] = 0.f; acc[mt][nt][1] = 0.f;
                    acc[mt][nt][2] = 0.f; acc[mt][nt][3] = 0.f;
                }
        }
    }

    // ---- epilogue ----
    if (MODE == 0) {
        #pragma unroll
        for (int mt = 0; mt < 2; mt++) {
            #pragma unroll
            for (int nt = 0; nt < 4; nt++) {
                int r0 = bm + wm * 32 + mt * 16 + g;
                int c0 = bn + wn * 32 + nt * 8 + 2 * t;
                __nv_bfloat162 v;
                v.x = __float2bfloat16_rn(acc[mt][nt][0]);
                v.y = __float2bfloat16_rn(acc[mt][nt][1]);
                *(__nv_bfloat162*)&g_Bu[(size_t)r0 * 1024 + c0] = v;
                v.x = __float2bfloat16_rn(acc[mt][nt][2]);
                v.y = __float2bfloat16_rn(acc[mt][nt][3]);
                *(__nv_bfloat162*)&g_Bu[(size_t)(r0 + 8) * 1024 + c0] = v;
            }
        }
    } else {
        #pragma unroll
        for (int mt = 0; mt < 2; mt++) {
            #pragma unroll
            for (int nt = 0; nt < 4; nt++) {
                int r0 = bm + wm * 32 + mt * 16 + g;
                int c0 = bn + wn * 32 + nt * 8 + 2 * t;
                float d0 = __ldg(Dv + c0), d1 = __ldg(Dv + c0 + 1);
                #pragma unroll
                for (int half = 0; half < 2; half++) {
                    int row = r0 + half * 8;
                    __nv_bfloat162 rrv = *(__nv_bfloat162*)&rrs[mt][nt][half];
                    __nv_bfloat16 ii0 = __float2bfloat16_rn(acc[mt][nt][2 * half]);
                    __nv_bfloat16 ii1 = __float2bfloat16_rn(acc[mt][nt][2 * half + 1]);
                    float db0 = __bfloat162float(__hsub(rrv.x, ii0));
                    float db1 = __bfloat162float(__hsub(rrv.y, ii1));
                    const float2 uu = *(const float2*)(u + (size_t)row * 1024 + c0);
                    float2 ov;
                    ov.x = fmaf(2.f, db0, d0 * uu.x);
                    ov.y = fmaf(2.f, db1, d1 * uu.y);
                    *(float2*)(out + (size_t)row * 1024 + c0) = ov;
                }
            }
        }
    }
}

// ---------------- scan: x_t = Lam*x_{t-1} + Bu_t; chunks of 64, batched loads ----------------
__global__ __launch_bounds__(512) void scan_pass1() {
    const int p = threadIdx.x;
    const int c = blockIdx.x;
    const float2 Lam = g_Lam[p];
    float xr = 0.f, xi = 0.f;
    const __nv_bfloat16* bu = g_Bu + (size_t)c * CHUNK * 1024;
    for (int tt = 0; tt < CHUNK; tt += 4) {
        float br[4], bi[4];
        #pragma unroll
        for (int j = 0; j < 4; j++) {
            br[j] = __bfloat162float(bu[(tt + j) * 1024 + p]);
            bi[j] = __bfloat162float(bu[(tt + j) * 1024 + 512 + p]);
        }
        #pragma unroll
        for (int j = 0; j < 4; j++) {
            float nr = fmaf(Lam.x, xr, fmaf(-Lam.y, xi, br[j]));
            float ni = fmaf(Lam.x, xi, fmaf(Lam.y, xr, bi[j]));
            xr = nr; xi = ni;
        }
    }
    g_End[c * PP + p] = make_float2(xr, xi);
}

// parallel carry scan: Carry[c] = sum_{j<c} W^{c-1-j} End[j], W = Lam^64.
// 256 blocks x 512 thr; block handles 2 channels x 256 chunk-positions (Kogge-Stone).
__global__ __launch_bounds__(512) void scan_pass2_par() {
    __shared__ float2 buf[512];
    const int t = threadIdx.x;
    const int ch = t >> 8;          // 0..1
    const int c  = t & 255;         // chunk position
    const int p  = blockIdx.x * 2 + ch;
    float2 Lam = g_Lam[p];
    float wr = Lam.x, wi = Lam.y;   // -> W = Lam^64 by 6 squarings
    #pragma unroll
    for (int s = 0; s < 6; s++) {
        float nr = wr * wr - wi * wi;
        float ni = 2.f * wr * wi;
        wr = nr; wi = ni;
    }
    float2 v = g_End[c * PP + p];
    float cr = wr, ci = wi;         // W^d, d = 1
    #pragma unroll
    for (int d = 1; d < 256; d <<= 1) {
        buf[t] = v;
        __syncthreads();
        if (c >= d) {
            float2 u2 = buf[t - d];
            float nx = fmaf(cr, u2.x, fmaf(-ci, u2.y, v.x));
            float ny = fmaf(cr, u2.y, fmaf(ci, u2.x, v.y));
            v.x = nx; v.y = ny;
        }
        __syncthreads();
        float nr = cr * cr - ci * ci;
        float ni = 2.f * cr * ci;
        cr = nr; ci = ni;
    }
    buf[t] = v;                     // inclusive[c]
    __syncthreads();
    float2 carry = (c == 0) ? make_float2(0.f, 0.f) : buf[t - 1];
    g_Carry[c * PP + p] = carry;
}

__global__ __launch_bounds__(512) void scan_pass3() {
    const int p = threadIdx.x;
    const int c = blockIdx.x;
    const float2 Lam = g_Lam[p];
    float2 cin = g_Carry[c * PP + p];
    float xr = cin.x, xi = cin.y;
    const __nv_bfloat16* bu = g_Bu + (size_t)c * CHUNK * 1024;
    __nv_bfloat16* xo = g_X + (size_t)c * CHUNK * 1024;
    for (int tt = 0; tt < CHUNK; tt += 4) {
        float br[4], bi[4];
        #pragma unroll
        for (int j = 0; j < 4; j++) {
            br[j] = __bfloat162float(bu[(tt + j) * 1024 + p]);
            bi[j] = __bfloat162float(bu[(tt + j) * 1024 + 512 + p]);
        }
        #pragma unroll
        for (int j = 0; j < 4; j++) {
            float nr = fmaf(Lam.x, xr, fmaf(-Lam.y, xi, br[j]));
            float ni = fmaf(Lam.x, xi, fmaf(Lam.y, xr, bi[j]));
            xr = nr; xi = ni;
            xo[(tt + j) * 1024 + p]       = __float2bfloat16_rn(xr);
            xo[(tt + j) * 1024 + 512 + p] = __float2bfloat16_rn(xi);
        }
    }
}

// ---------------- launch ----------------
extern "C" void kernel_launch(void* const* d_in, const int* in_sizes, int n_in,
                              void* d_out, int out_size) {
    const float* u       = (const float*)d_in[0];
    const float* LamRe   = (const float*)d_in[1];
    const float* LamIm   = (const float*)d_in[2];
    const float* B_re    = (const float*)d_in[3];
    const float* B_im    = (const float*)d_in[4];
    const float* C_re    = (const float*)d_in[5];
    const float* C_im    = (const float*)d_in[6];
    const float* Dv      = (const float*)d_in[7];
    const float* logstep = (const float*)d_in[8];
    float* out = (float*)d_out;

    prep_lambda_kernel<<<1, 512>>>(LamRe, LamIm, logstep);
    prep_BC_kernel<<<(PP * HH) / 256, 256>>>(B_re, B_im, C_re, C_im);
    prep_U_kernel<<<(LL * HH) / 8 / 256, 256>>>(u);

    cudaFuncSetAttribute(gemm_hmma_kernel<0>, cudaFuncAttributeMaxDynamicSharedMemorySize, GSMEM);
    gemm_hmma_kernel<0><<<dim3(LL / 128, 8), 512, GSMEM>>>(nullptr, nullptr, nullptr);

    scan_pass1<<<NCHUNK, PP>>>();
    scan_pass2_par<<<PP / 2, 512>>>();
    scan_pass3<<<NCHUNK, PP>>>();

    cudaFuncSetAttribute(gemm_hmma_kernel<1>, cudaFuncAttributeMaxDynamicSharedMemorySize, GSMEM);
    gemm_hmma_kernel<1><<<dim3(LL / 128, 8), 512, GSMEM>>>(u, Dv, out);
}